// round 7
// baseline (speedup 1.0000x reference)
#include <cuda_runtime.h>
#include <cuda_bf16.h>
#include <math.h>
#include <stdint.h>

#define DIM      128
#define N_DIAG   30000
#define N_PRO    20000
#define N_NODES  50000
#define N_EDGES  800000
#define N_REL    8
#define T_VISITS 2
#define NCOLS    (N_REL * DIM + DIM)   // 1152: 8 relation blocks + root block
#define VOC_DIAG 2000
#define VOC_PRO  1500
#define VOC3     150

// ---------------- scratch (static device globals; 16B-aligned for float4 access) ----
// RULES LEARNED (hard way):
//  1. NO CUDA API calls before main() — a pre-registration runtime init leaves this
//     module's kernels unloadable ("invalid resource handle" on every launch).
//  2. NO register caps that cause spills — ~448 B/thread spill grew the driver
//     local-memory pool by 134 MiB at first launch -> harness checkpoint violation.
//  3. From HOST code, pass device globals via cudaGetSymbolAddress, never by name.
__device__ __align__(16) float g_x [N_NODES * DIM];
__device__ __align__(16) float g_y [N_NODES * DIM];
__device__ __align__(16) float g_xw[(size_t)N_NODES * N_REL * DIM];
__device__ __align__(16) int   g_cnt[N_NODES * N_REL];
__device__ __align__(16) float g_Wbig[2][DIM * NCOLS];
__device__ __align__(16) float g_cread[DIM];
__device__ __align__(16) float g_h[DIM];

// ---------------- repack W: Wbig[d*1152 + c] ----------------
__global__ void prep_wbig_kernel(const float* __restrict__ W,
                                 const float* __restrict__ root,
                                 float* __restrict__ out)
{
    int idx = blockIdx.x * blockDim.x + threadIdx.x;
    if (idx >= DIM * NCOLS) return;
    int d = idx / NCOLS;
    int c = idx % NCOLS;
    float v;
    if (c < N_REL * DIM) {
        int r = c >> 7, o = c & 127;
        v = W[(size_t)r * DIM * DIM + d * DIM + o];
    } else {
        v = root[d * DIM + (c - N_REL * DIM)];
    }
    out[idx] = v;
}

// ---------------- gather x = concat(diag_emb[idx], pro_emb[idx]) ----------------
__global__ void gather_kernel(const int* __restrict__ diag_idx,
                              const int* __restrict__ pro_idx,
                              const float* __restrict__ diag_emb,
                              const float* __restrict__ pro_emb)
{
    int i = blockIdx.x * blockDim.x + threadIdx.x;   // over N_NODES * 32 float4s
    if (i >= N_NODES * 32) return;
    int node = i >> 5;
    int f4   = i & 31;
    const float* srcrow;
    if (node < N_DIAG) {
        int idx = min(max(diag_idx[node], 0), VOC_DIAG - 1);
        srcrow = diag_emb + (size_t)idx * DIM;
    } else {
        int idx = min(max(pro_idx[node - N_DIAG], 0), VOC_PRO - 1);
        srcrow = pro_emb + (size_t)idx * DIM;
    }
    ((float4*)(g_x + (size_t)node * DIM))[f4] = ((const float4*)srcrow)[f4];
}

// ---------------- histogram of (dst, etype) ----------------
__global__ void hist_kernel(const int* __restrict__ dst, const int* __restrict__ et)
{
    int e = blockIdx.x * blockDim.x + threadIdx.x;
    if (e >= N_EDGES) return;
    int d = min(max(dst[e], 0), N_NODES - 1);
    int r = et[e] & (N_REL - 1);
    atomicAdd(&g_cnt[d * N_REL + r], 1);
}

// ---------------- GEMM: [M,128] x [128,1152] -> xw (cols<1024) and y (cols>=1024,+bias)
#define BM 128
#define BN 64
#define BK 32
#define GEMM_GRID_X (NCOLS / BN)                       // 18
#define GEMM_GRID_Y ((N_NODES + BM - 1) / BM)          // 391
__global__ __launch_bounds__(256)
void gemm_kernel(const float* __restrict__ A, const float* __restrict__ B,
                 const float* __restrict__ bias)
{
    __shared__ float As[BK][BM + 4];
    __shared__ float Bs[BK][BN];

    const int block_m = blockIdx.y * BM;
    const int block_n = blockIdx.x * BN;
    const int tid = threadIdx.x;
    const int tx = tid & 15;   // n
    const int ty = tid >> 4;   // m

    float acc[8][4];
#pragma unroll
    for (int m = 0; m < 8; m++)
#pragma unroll
        for (int n = 0; n < 4; n++) acc[m][n] = 0.f;

    for (int kb = 0; kb < DIM; kb += BK) {
#pragma unroll
        for (int i = 0; i < 4; i++) {
            int fid = tid + i * 256;          // 0..1023
            int r   = fid >> 3;               // row in tile
            int c   = (fid & 7) * 4;          // k offset
            float4 v = make_float4(0.f, 0.f, 0.f, 0.f);
            if (block_m + r < N_NODES)
                v = *(const float4*)(A + (size_t)(block_m + r) * DIM + kb + c);
            As[c + 0][r] = v.x; As[c + 1][r] = v.y;
            As[c + 2][r] = v.z; As[c + 3][r] = v.w;
        }
#pragma unroll
        for (int i = 0; i < 2; i++) {
            int fid = tid + i * 256;          // 0..511
            int r   = fid >> 4;
            int c   = (fid & 15) * 4;
            *(float4*)(&Bs[r][c]) =
                *(const float4*)(B + (size_t)(kb + r) * NCOLS + block_n + c);
        }
        __syncthreads();

#pragma unroll
        for (int k = 0; k < BK; k++) {
            float4 a0 = *(const float4*)(&As[k][ty * 8]);
            float4 a1 = *(const float4*)(&As[k][ty * 8 + 4]);
            float4 b  = *(const float4*)(&Bs[k][tx * 4]);
            float am[8] = {a0.x, a0.y, a0.z, a0.w, a1.x, a1.y, a1.z, a1.w};
#pragma unroll
            for (int m = 0; m < 8; m++) {
                acc[m][0] = fmaf(am[m], b.x, acc[m][0]);
                acc[m][1] = fmaf(am[m], b.y, acc[m][1]);
                acc[m][2] = fmaf(am[m], b.z, acc[m][2]);
                acc[m][3] = fmaf(am[m], b.w, acc[m][3]);
            }
        }
        __syncthreads();
    }

    const int col = block_n + tx * 4;
#pragma unroll
    for (int m = 0; m < 8; m++) {
        int row = block_m + ty * 8 + m;
        if (row >= N_NODES) continue;
        float4 v = make_float4(acc[m][0], acc[m][1], acc[m][2], acc[m][3]);
        if (col < N_REL * DIM) {
            *(float4*)(g_xw + (size_t)row * (N_REL * DIM) + col) = v;
        } else {
            int cc = col - N_REL * DIM;
            float4 bv = *(const float4*)(bias + cc);
            v.x += bv.x; v.y += bv.y; v.z += bv.z; v.w += bv.w;
            *(float4*)(g_y + (size_t)row * DIM + cc) = v;
        }
    }
}

// ---------------- edge scatter: y[dst] += norm * xw[src, et] (warp per edge) ----
#define EDGE_BLOCKS ((int)(((long long)N_EDGES * 32 + 255) / 256))   // 100000
__global__ __launch_bounds__(256)
void edge_kernel(const int* __restrict__ src, const int* __restrict__ dst,
                 const int* __restrict__ et, int n_edges)
{
    int gtid = blockIdx.x * blockDim.x + threadIdx.x;
    int e    = gtid >> 5;
    int lane = gtid & 31;
    if (e >= n_edges) return;
    int s = min(max(__ldg(src + e), 0), N_NODES - 1);
    int d = min(max(__ldg(dst + e), 0), N_NODES - 1);
    int r = __ldg(et + e) & (N_REL - 1);
    int cnt = __ldg(&g_cnt[d * N_REL + r]);
    float norm = 1.0f / (float)max(cnt, 1);
    float4 v = *(const float4*)(g_xw + (size_t)s * (N_REL * DIM) + r * DIM + lane * 4);
    float* p = g_y + (size_t)d * DIM + lane * 4;
    atomicAdd(p + 0, v.x * norm);
    atomicAdd(p + 1, v.y * norm);
    atomicAdd(p + 2, v.z * norm);
    atomicAdd(p + 3, v.w * norm);
}

// ---------------- relu (+ optional column-sum readout) ----------------
#define RELU_ROWS 32
#define RELU_BLOCKS ((N_NODES + RELU_ROWS - 1) / RELU_ROWS)         // 1563
__global__ void relu_kernel(int do_readout)
{
    int col  = threadIdx.x;              // 128
    int row0 = blockIdx.x * RELU_ROWS;
    float sum = 0.f;
#pragma unroll 4
    for (int i = 0; i < RELU_ROWS; i++) {
        int row = row0 + i;
        if (row >= N_NODES) break;
        float v = g_y[(size_t)row * DIM + col];
        v = fmaxf(v, 0.f);
        g_x[(size_t)row * DIM + col] = v;
        sum += v;
    }
    if (do_readout) atomicAdd(&g_cread[col], sum);
}

// ---------------- GRU cell (single block, 128 threads) ----------------
__global__ void gru_kernel(const float* __restrict__ Wih, const float* __restrict__ Whh,
                           const float* __restrict__ bih, const float* __restrict__ bhh)
{
    __shared__ float c[DIM], hh[DIM];
    int tid = threadIdx.x;
    c[tid]  = g_cread[tid];
    hh[tid] = g_h[tid];
    __syncthreads();

    float gi[3], gh[3];
#pragma unroll
    for (int g = 0; g < 3; g++) {
        int row = g * DIM + tid;
        float si = bih[row], sh = bhh[row];
        const float* wi = Wih + (size_t)row * DIM;
        const float* wh = Whh + (size_t)row * DIM;
        for (int d = 0; d < DIM; d++) {
            si = fmaf(c[d],  wi[d], si);
            sh = fmaf(hh[d], wh[d], sh);
        }
        gi[g] = si; gh[g] = sh;
    }
    float r = 1.0f / (1.0f + expf(-(gi[0] + gh[0])));
    float z = 1.0f / (1.0f + expf(-(gi[1] + gh[1])));
    float n = tanhf(gi[2] + r * gh[2]);
    float hn = (1.0f - z) * n + z * hh[tid];
    __syncthreads();
    g_h[tid] = hn;
}

// ---------------- output head (single block, 256 threads) ----------------
__global__ void out_kernel(const float* __restrict__ Wo1, const float* __restrict__ bo1,
                           const float* __restrict__ Wo2, const float* __restrict__ bo2,
                           float* __restrict__ out)
{
    __shared__ float hs[DIM], tmp[2 * DIM];
    int tid = threadIdx.x;
    if (tid < DIM) hs[tid] = g_h[tid];
    __syncthreads();
    {
        float a = bo1[tid];
        const float* w = Wo1 + (size_t)tid * DIM;
        for (int d = 0; d < DIM; d++) a = fmaf(hs[d], w[d], a);
        tmp[tid] = fmaxf(a, 0.f);
    }
    __syncthreads();
    if (tid < VOC3) {
        float o = bo2[tid];
        const float* w = Wo2 + (size_t)tid * 2 * DIM;
        for (int j = 0; j < 2 * DIM; j++) o = fmaf(tmp[j], w[j], o);
        out[tid] = o;
    }
}

// =============================== host launcher ===============================
extern "C" void kernel_launch(void* const* d_in, const int* in_sizes, int n_in,
                              void* d_out, int out_size)
{
    const int*   c_diag_idx   = (const int*)  d_in[0];
    const int*   c_pro_idx    = (const int*)  d_in[1];
    const int*   c_edge_index = (const int*)  d_in[2];
    const int*   c_edge_type  = (const int*)  d_in[3];
    const float* diag_emb     = (const float*)d_in[4];
    const float* pro_emb      = (const float*)d_in[5];
    const float* W1           = (const float*)d_in[6];
    const float* root1        = (const float*)d_in[7];
    const float* b1           = (const float*)d_in[8];
    const float* W2           = (const float*)d_in[9];
    const float* root2        = (const float*)d_in[10];
    const float* b2           = (const float*)d_in[11];
    const float* gru_Wih      = (const float*)d_in[12];
    const float* gru_Whh      = (const float*)d_in[13];
    const float* gru_bih      = (const float*)d_in[14];
    const float* gru_bhh      = (const float*)d_in[15];
    const float* Wo1          = (const float*)d_in[16];
    const float* bo1          = (const float*)d_in[17];
    const float* Wo2          = (const float*)d_in[18];
    const float* bo2          = (const float*)d_in[19];
    float* out = (float*)d_out;

    void *p_x, *p_cnt, *p_cread, *p_h, *p_wbig;
    cudaGetSymbolAddress(&p_x,     g_x);
    cudaGetSymbolAddress(&p_cnt,   g_cnt);
    cudaGetSymbolAddress(&p_cread, g_cread);
    cudaGetSymbolAddress(&p_h,     g_h);
    cudaGetSymbolAddress(&p_wbig,  g_Wbig);
    const float* x_dev = (const float*)p_x;
    float* wbig0 = (float*)p_wbig;
    float* wbig1 = wbig0 + DIM * NCOLS;

    {
        int n = DIM * NCOLS;
        prep_wbig_kernel<<<(n + 255) / 256, 256>>>(W1, root1, wbig0);
        prep_wbig_kernel<<<(n + 255) / 256, 256>>>(W2, root2, wbig1);
    }
    cudaMemsetAsync(p_h, 0, DIM * sizeof(float));

    const float* wbig[2] = {wbig0, wbig1};
    const float* bias[2] = {b1, b2};

    for (int t = 0; t < T_VISITS; t++) {
        const int* diag_t = c_diag_idx + (size_t)t * N_DIAG;
        const int* pro_t  = c_pro_idx  + (size_t)t * N_PRO;
        const int* src_t  = c_edge_index + (size_t)t * 2 * N_EDGES;
        const int* dst_t  = src_t + N_EDGES;
        const int* et_t   = c_edge_type + (size_t)t * N_EDGES;

        gather_kernel<<<(N_NODES * 32 + 255) / 256, 256>>>(diag_t, pro_t, diag_emb, pro_emb);

        cudaMemsetAsync(p_cnt, 0, N_NODES * N_REL * sizeof(int));
        hist_kernel<<<(N_EDGES + 255) / 256, 256>>>(dst_t, et_t);
        cudaMemsetAsync(p_cread, 0, DIM * sizeof(float));

        for (int l = 0; l < 2; l++) {
            gemm_kernel<<<dim3(GEMM_GRID_X, GEMM_GRID_Y), 256>>>(x_dev, wbig[l], bias[l]);
            edge_kernel<<<EDGE_BLOCKS, 256>>>(src_t, dst_t, et_t, N_EDGES);
            relu_kernel<<<RELU_BLOCKS, DIM>>>(l == 1 ? 1 : 0);
        }
        gru_kernel<<<1, DIM>>>(gru_Wih, gru_Whh, gru_bih, gru_bhh);
    }
    out_kernel<<<1, 2 * DIM>>>(Wo1, bo1, Wo2, bo2, out);
}

// round 8
// speedup vs baseline: 1.3588x; 1.3588x over previous
#include <cuda_runtime.h>
#include <cuda_bf16.h>
#include <math.h>
#include <stdint.h>

#define DIM      128
#define N_DIAG   30000
#define N_PRO    20000
#define N_NODES  50000
#define N_EDGES  800000
#define N_REL    8
#define T_VISITS 2
#define NCOLS    (N_REL * DIM + DIM)   // 1152: 8 relation blocks + root block
#define VOC_DIAG 2000
#define VOC_PRO  1500
#define TAB_ROWS (VOC_DIAG + VOC_PRO)  // 3500 distinct embedding rows
#define VOC3     150

// RULES LEARNED (hard way):
//  1. NO CUDA API calls before main() — pre-registration runtime init leaves this
//     module's kernels unloadable ("invalid resource handle" on every launch).
//  2. NO register caps that cause spills — ~448 B/thread spill grew the driver
//     local-memory pool by 134 MiB at first launch -> harness checkpoint violation.
//  3. From HOST code, pass device globals via cudaGetSymbolAddress, never by name.
__device__ __align__(16) float g_x  [N_NODES * DIM];                 // layer-2 input
__device__ __align__(16) float g_y  [N_NODES * DIM];                 // layer accumulator
__device__ __align__(16) float g_xw [(size_t)N_NODES * N_REL * DIM]; // layer-2 transforms
__device__ __align__(16) float g_tab[TAB_ROWS * NCOLS];              // layer-1 dedup table
__device__ __align__(16) int   g_map[N_NODES];                       // node -> table row
__device__ __align__(16) int   g_cnt[N_NODES * N_REL];
__device__ __align__(16) float g_Wbig[2][DIM * NCOLS];
__device__ __align__(16) float g_cread[DIM];
__device__ __align__(16) float g_h[DIM];

// ---------------- repack W: Wbig[d*1152 + c] = [W_r | root] ----------------
__global__ void prep_wbig_kernel(const float* __restrict__ W,
                                 const float* __restrict__ root,
                                 float* __restrict__ out)
{
    int idx = blockIdx.x * blockDim.x + threadIdx.x;
    if (idx >= DIM * NCOLS) return;
    int d = idx / NCOLS;
    int c = idx % NCOLS;
    float v;
    if (c < N_REL * DIM) {
        int r = c >> 7, o = c & 127;
        v = W[(size_t)r * DIM * DIM + d * DIM + o];
    } else {
        v = root[d * DIM + (c - N_REL * DIM)];
    }
    out[idx] = v;
}

// ---------------- node -> embedding-table row map ----------------
__global__ void map_kernel(const int* __restrict__ diag_idx,
                           const int* __restrict__ pro_idx)
{
    int n = blockIdx.x * blockDim.x + threadIdx.x;
    if (n >= N_NODES) return;
    int m;
    if (n < N_DIAG) m = min(max(diag_idx[n], 0), VOC_DIAG - 1);
    else            m = VOC_DIAG + min(max(pro_idx[n - N_DIAG], 0), VOC_PRO - 1);
    g_map[n] = m;
}

// ---------------- layer-1 y init: y[n] = tab[map[n], root block] (bias baked in) ----
__global__ void yinit_kernel()
{
    int i = blockIdx.x * blockDim.x + threadIdx.x;   // over N_NODES * 32 float4s
    if (i >= N_NODES * 32) return;
    int node = i >> 5;
    int f4   = i & 31;
    const float4* srow = (const float4*)(g_tab + (size_t)g_map[node] * NCOLS + N_REL * DIM);
    ((float4*)(g_y + (size_t)node * DIM))[f4] = srow[f4];
}

// ---------------- histogram of (dst, etype) ----------------
__global__ void hist_kernel(const int* __restrict__ dst, const int* __restrict__ et)
{
    int e = blockIdx.x * blockDim.x + threadIdx.x;
    if (e >= N_EDGES) return;
    int d = min(max(dst[e], 0), N_NODES - 1);
    int r = et[e] & (N_REL - 1);
    atomicAdd(&g_cnt[d * N_REL + r], 1);
}

// ======== table GEMM: [3500,128](embeddings) x [128,1152] -> g_tab (+bias on root) ====
#define BM 128
#define BN 64
#define BK 32
#define TAB_GRID_Y ((TAB_ROWS + BM - 1) / BM)          // 28
__global__ __launch_bounds__(256)
void tabgemm_kernel(const float* __restrict__ diag_emb,
                    const float* __restrict__ pro_emb,
                    const float* __restrict__ Bmat,
                    const float* __restrict__ bias)
{
    __shared__ float As[BK][BM + 4];
    __shared__ float Bs[BK][BN];

    const int block_m = blockIdx.y * BM;
    const int block_n = blockIdx.x * BN;
    const int tid = threadIdx.x;
    const int tx = tid & 15;
    const int ty = tid >> 4;

    float acc[8][4];
#pragma unroll
    for (int m = 0; m < 8; m++)
#pragma unroll
        for (int n = 0; n < 4; n++) acc[m][n] = 0.f;

    for (int kb = 0; kb < DIM; kb += BK) {
#pragma unroll
        for (int i = 0; i < 4; i++) {
            int fid = tid + i * 256;
            int r   = fid >> 3;
            int c   = (fid & 7) * 4;
            int row = block_m + r;
            float4 v = make_float4(0.f, 0.f, 0.f, 0.f);
            if (row < TAB_ROWS) {
                const float* srow = (row < VOC_DIAG)
                    ? diag_emb + (size_t)row * DIM
                    : pro_emb  + (size_t)(row - VOC_DIAG) * DIM;
                v = *(const float4*)(srow + kb + c);
            }
            As[c + 0][r] = v.x; As[c + 1][r] = v.y;
            As[c + 2][r] = v.z; As[c + 3][r] = v.w;
        }
#pragma unroll
        for (int i = 0; i < 2; i++) {
            int fid = tid + i * 256;
            int r   = fid >> 4;
            int c   = (fid & 15) * 4;
            *(float4*)(&Bs[r][c]) =
                *(const float4*)(Bmat + (size_t)(kb + r) * NCOLS + block_n + c);
        }
        __syncthreads();

#pragma unroll
        for (int k = 0; k < BK; k++) {
            float4 a0 = *(const float4*)(&As[k][ty * 8]);
            float4 a1 = *(const float4*)(&As[k][ty * 8 + 4]);
            float4 b  = *(const float4*)(&Bs[k][tx * 4]);
            float am[8] = {a0.x, a0.y, a0.z, a0.w, a1.x, a1.y, a1.z, a1.w};
#pragma unroll
            for (int m = 0; m < 8; m++) {
                acc[m][0] = fmaf(am[m], b.x, acc[m][0]);
                acc[m][1] = fmaf(am[m], b.y, acc[m][1]);
                acc[m][2] = fmaf(am[m], b.z, acc[m][2]);
                acc[m][3] = fmaf(am[m], b.w, acc[m][3]);
            }
        }
        __syncthreads();
    }

    const int col = block_n + tx * 4;
#pragma unroll
    for (int m = 0; m < 8; m++) {
        int row = block_m + ty * 8 + m;
        if (row >= TAB_ROWS) continue;
        float4 v = make_float4(acc[m][0], acc[m][1], acc[m][2], acc[m][3]);
        if (col >= N_REL * DIM) {               // root block: bake bias in
            float4 bv = *(const float4*)(bias + (col - N_REL * DIM));
            v.x += bv.x; v.y += bv.y; v.z += bv.z; v.w += bv.w;
        }
        *(float4*)(g_tab + (size_t)row * NCOLS + col) = v;
    }
}

// ======== layer-2 GEMM: [50000,128] x [128,1152] -> xw (cols<1024) and y (+bias) ======
#define GEMM_GRID_X (NCOLS / BN)                       // 18
#define GEMM_GRID_Y ((N_NODES + BM - 1) / BM)          // 391
__global__ __launch_bounds__(256)
void gemm_kernel(const float* __restrict__ A, const float* __restrict__ B,
                 const float* __restrict__ bias)
{
    __shared__ float As[BK][BM + 4];
    __shared__ float Bs[BK][BN];

    const int block_m = blockIdx.y * BM;
    const int block_n = blockIdx.x * BN;
    const int tid = threadIdx.x;
    const int tx = tid & 15;
    const int ty = tid >> 4;

    float acc[8][4];
#pragma unroll
    for (int m = 0; m < 8; m++)
#pragma unroll
        for (int n = 0; n < 4; n++) acc[m][n] = 0.f;

    for (int kb = 0; kb < DIM; kb += BK) {
#pragma unroll
        for (int i = 0; i < 4; i++) {
            int fid = tid + i * 256;
            int r   = fid >> 3;
            int c   = (fid & 7) * 4;
            float4 v = make_float4(0.f, 0.f, 0.f, 0.f);
            if (block_m + r < N_NODES)
                v = *(const float4*)(A + (size_t)(block_m + r) * DIM + kb + c);
            As[c + 0][r] = v.x; As[c + 1][r] = v.y;
            As[c + 2][r] = v.z; As[c + 3][r] = v.w;
        }
#pragma unroll
        for (int i = 0; i < 2; i++) {
            int fid = tid + i * 256;
            int r   = fid >> 4;
            int c   = (fid & 15) * 4;
            *(float4*)(&Bs[r][c]) =
                *(const float4*)(B + (size_t)(kb + r) * NCOLS + block_n + c);
        }
        __syncthreads();

#pragma unroll
        for (int k = 0; k < BK; k++) {
            float4 a0 = *(const float4*)(&As[k][ty * 8]);
            float4 a1 = *(const float4*)(&As[k][ty * 8 + 4]);
            float4 b  = *(const float4*)(&Bs[k][tx * 4]);
            float am[8] = {a0.x, a0.y, a0.z, a0.w, a1.x, a1.y, a1.z, a1.w};
#pragma unroll
            for (int m = 0; m < 8; m++) {
                acc[m][0] = fmaf(am[m], b.x, acc[m][0]);
                acc[m][1] = fmaf(am[m], b.y, acc[m][1]);
                acc[m][2] = fmaf(am[m], b.z, acc[m][2]);
                acc[m][3] = fmaf(am[m], b.w, acc[m][3]);
            }
        }
        __syncthreads();
    }

    const int col = block_n + tx * 4;
#pragma unroll
    for (int m = 0; m < 8; m++) {
        int row = block_m + ty * 8 + m;
        if (row >= N_NODES) continue;
        float4 v = make_float4(acc[m][0], acc[m][1], acc[m][2], acc[m][3]);
        if (col < N_REL * DIM) {
            *(float4*)(g_xw + (size_t)row * (N_REL * DIM) + col) = v;
        } else {
            int cc = col - N_REL * DIM;
            float4 bv = *(const float4*)(bias + cc);
            v.x += bv.x; v.y += bv.y; v.z += bv.z; v.w += bv.w;
            *(float4*)(g_y + (size_t)row * DIM + cc) = v;
        }
    }
}

// ---------------- edge scatter: y[dst] += norm * XW[row(src), et] (warp/edge) ----
// use_map != 0 -> row = g_map[src], XW row stride NCOLS (layer-1 table, L2-resident)
// use_map == 0 -> row = src,        XW row stride N_REL*DIM (layer-2 xw)
#define EDGE_BLOCKS ((int)(((long long)N_EDGES * 32 + 255) / 256))   // 100000
__global__ __launch_bounds__(256)
void edge_kernel(const int* __restrict__ src, const int* __restrict__ dst,
                 const int* __restrict__ et,
                 const float* __restrict__ XW, int row_stride, int use_map)
{
    int gtid = blockIdx.x * blockDim.x + threadIdx.x;
    int e    = gtid >> 5;
    int lane = gtid & 31;
    if (e >= N_EDGES) return;
    int s = min(max(__ldg(src + e), 0), N_NODES - 1);
    int d = min(max(__ldg(dst + e), 0), N_NODES - 1);
    int r = __ldg(et + e) & (N_REL - 1);
    if (use_map) s = __ldg(&g_map[s]);
    int cnt = __ldg(&g_cnt[d * N_REL + r]);
    float norm = 1.0f / (float)max(cnt, 1);
    float4 v = *(const float4*)(XW + (size_t)s * row_stride + r * DIM + lane * 4);
    float* p = g_y + (size_t)d * DIM + lane * 4;
    atomicAdd(p + 0, v.x * norm);
    atomicAdd(p + 1, v.y * norm);
    atomicAdd(p + 2, v.z * norm);
    atomicAdd(p + 3, v.w * norm);
}

// ---------------- relu (+ optional column-sum readout) ----------------
#define RELU_ROWS 32
#define RELU_BLOCKS ((N_NODES + RELU_ROWS - 1) / RELU_ROWS)         // 1563
__global__ void relu_kernel(int do_readout)
{
    int col  = threadIdx.x;              // 128
    int row0 = blockIdx.x * RELU_ROWS;
    float sum = 0.f;
#pragma unroll 4
    for (int i = 0; i < RELU_ROWS; i++) {
        int row = row0 + i;
        if (row >= N_NODES) break;
        float v = g_y[(size_t)row * DIM + col];
        v = fmaxf(v, 0.f);
        g_x[(size_t)row * DIM + col] = v;
        sum += v;
    }
    if (do_readout) atomicAdd(&g_cread[col], sum);
}

// ---------------- GRU cell (single block, 128 threads) ----------------
__global__ void gru_kernel(const float* __restrict__ Wih, const float* __restrict__ Whh,
                           const float* __restrict__ bih, const float* __restrict__ bhh)
{
    __shared__ float c[DIM], hh[DIM];
    int tid = threadIdx.x;
    c[tid]  = g_cread[tid];
    hh[tid] = g_h[tid];
    __syncthreads();

    float gi[3], gh[3];
#pragma unroll
    for (int g = 0; g < 3; g++) {
        int row = g * DIM + tid;
        float si = bih[row], sh = bhh[row];
        const float* wi = Wih + (size_t)row * DIM;
        const float* wh = Whh + (size_t)row * DIM;
        for (int d = 0; d < DIM; d++) {
            si = fmaf(c[d],  wi[d], si);
            sh = fmaf(hh[d], wh[d], sh);
        }
        gi[g] = si; gh[g] = sh;
    }
    float r = 1.0f / (1.0f + expf(-(gi[0] + gh[0])));
    float z = 1.0f / (1.0f + expf(-(gi[1] + gh[1])));
    float n = tanhf(gi[2] + r * gh[2]);
    float hn = (1.0f - z) * n + z * hh[tid];
    __syncthreads();
    g_h[tid] = hn;
}

// ---------------- output head (single block, 256 threads) ----------------
__global__ void out_kernel(const float* __restrict__ Wo1, const float* __restrict__ bo1,
                           const float* __restrict__ Wo2, const float* __restrict__ bo2,
                           float* __restrict__ out)
{
    __shared__ float hs[DIM], tmp[2 * DIM];
    int tid = threadIdx.x;
    if (tid < DIM) hs[tid] = g_h[tid];
    __syncthreads();
    {
        float a = bo1[tid];
        const float* w = Wo1 + (size_t)tid * DIM;
        for (int d = 0; d < DIM; d++) a = fmaf(hs[d], w[d], a);
        tmp[tid] = fmaxf(a, 0.f);
    }
    __syncthreads();
    if (tid < VOC3) {
        float o = bo2[tid];
        const float* w = Wo2 + (size_t)tid * 2 * DIM;
        for (int j = 0; j < 2 * DIM; j++) o = fmaf(tmp[j], w[j], o);
        out[tid] = o;
    }
}

// =============================== host launcher ===============================
extern "C" void kernel_launch(void* const* d_in, const int* in_sizes, int n_in,
                              void* d_out, int out_size)
{
    const int*   c_diag_idx   = (const int*)  d_in[0];
    const int*   c_pro_idx    = (const int*)  d_in[1];
    const int*   c_edge_index = (const int*)  d_in[2];
    const int*   c_edge_type  = (const int*)  d_in[3];
    const float* diag_emb     = (const float*)d_in[4];
    const float* pro_emb      = (const float*)d_in[5];
    const float* W1           = (const float*)d_in[6];
    const float* root1        = (const float*)d_in[7];
    const float* b1           = (const float*)d_in[8];
    const float* W2           = (const float*)d_in[9];
    const float* root2        = (const float*)d_in[10];
    const float* b2           = (const float*)d_in[11];
    const float* gru_Wih      = (const float*)d_in[12];
    const float* gru_Whh      = (const float*)d_in[13];
    const float* gru_bih      = (const float*)d_in[14];
    const float* gru_bhh      = (const float*)d_in[15];
    const float* Wo1          = (const float*)d_in[16];
    const float* bo1          = (const float*)d_in[17];
    const float* Wo2          = (const float*)d_in[18];
    const float* bo2          = (const float*)d_in[19];
    float* out = (float*)d_out;

    void *p_x, *p_tab, *p_xw, *p_cnt, *p_cread, *p_h, *p_wbig;
    cudaGetSymbolAddress(&p_x,     g_x);
    cudaGetSymbolAddress(&p_tab,   g_tab);
    cudaGetSymbolAddress(&p_xw,    g_xw);
    cudaGetSymbolAddress(&p_cnt,   g_cnt);
    cudaGetSymbolAddress(&p_cread, g_cread);
    cudaGetSymbolAddress(&p_h,     g_h);
    cudaGetSymbolAddress(&p_wbig,  g_Wbig);
    const float* x_dev   = (const float*)p_x;
    const float* tab_dev = (const float*)p_tab;
    const float* xw_dev  = (const float*)p_xw;
    float* wbig0 = (float*)p_wbig;
    float* wbig1 = wbig0 + DIM * NCOLS;

    // once per call: repack weights; build layer-1 dedup table (visit-independent!)
    {
        int n = DIM * NCOLS;
        prep_wbig_kernel<<<(n + 255) / 256, 256>>>(W1, root1, wbig0);
        prep_wbig_kernel<<<(n + 255) / 256, 256>>>(W2, root2, wbig1);
    }
    tabgemm_kernel<<<dim3(GEMM_GRID_X, TAB_GRID_Y), 256>>>(diag_emb, pro_emb, wbig0, b1);
    cudaMemsetAsync(p_h, 0, DIM * sizeof(float));

    for (int t = 0; t < T_VISITS; t++) {
        const int* diag_t = c_diag_idx + (size_t)t * N_DIAG;
        const int* pro_t  = c_pro_idx  + (size_t)t * N_PRO;
        const int* src_t  = c_edge_index + (size_t)t * 2 * N_EDGES;
        const int* dst_t  = src_t + N_EDGES;
        const int* et_t   = c_edge_type + (size_t)t * N_EDGES;

        map_kernel<<<(N_NODES + 255) / 256, 256>>>(diag_t, pro_t);

        cudaMemsetAsync(p_cnt, 0, N_NODES * N_REL * sizeof(int));
        hist_kernel<<<(N_EDGES + 255) / 256, 256>>>(dst_t, et_t);
        cudaMemsetAsync(p_cread, 0, DIM * sizeof(float));

        // ---- layer 1 (deduplicated via table) ----
        yinit_kernel<<<(N_NODES * 32 + 255) / 256, 256>>>();
        edge_kernel<<<EDGE_BLOCKS, 256>>>(src_t, dst_t, et_t, tab_dev, NCOLS, 1);
        relu_kernel<<<RELU_BLOCKS, DIM>>>(0);

        // ---- layer 2 (full GEMM) ----
        gemm_kernel<<<dim3(GEMM_GRID_X, GEMM_GRID_Y), 256>>>(x_dev, wbig1, b2);
        edge_kernel<<<EDGE_BLOCKS, 256>>>(src_t, dst_t, et_t, xw_dev, N_REL * DIM, 0);
        relu_kernel<<<RELU_BLOCKS, DIM>>>(1);

        gru_kernel<<<1, DIM>>>(gru_Wih, gru_Whh, gru_bih, gru_bhh);
    }
    out_kernel<<<1, 2 * DIM>>>(Wo1, bo1, Wo2, bo2, out);
}

// round 9
// speedup vs baseline: 1.6293x; 1.1991x over previous
#include <cuda_runtime.h>
#include <cuda_bf16.h>
#include <math.h>
#include <stdint.h>

#define DIM      128
#define N_DIAG   30000
#define N_PRO    20000
#define N_NODES  50000
#define N_EDGES  800000
#define N_REL    8
#define T_VISITS 2
#define NCOLS    (N_REL * DIM + DIM)   // 1152: 8 relation blocks + root block
#define NRD      (N_REL * DIM)         // 1024
#define VOC_DIAG 2000
#define VOC_PRO  1500
#define TAB_ROWS (VOC_DIAG + VOC_PRO)  // 3500 distinct embedding rows
#define VOC3     150

// RULES LEARNED (hard way):
//  1. NO CUDA API calls before main() — pre-registration runtime init leaves this
//     module's kernels unloadable ("invalid resource handle" on every launch).
//  2. NO register caps that cause spills — ~448 B/thread spill grew the driver
//     local-memory pool by 134 MiB at first launch -> harness checkpoint violation.
//  3. From HOST code, pass device globals via cudaGetSymbolAddress, never by name.
__device__ __align__(16) float g_x  [N_NODES * DIM];                 // layer-2 input
__device__ __align__(16) float g_y  [N_NODES * DIM];                 // layer accumulator
__device__ __align__(16) float g_xw [(size_t)N_NODES * N_REL * DIM]; // layer-2 transforms
__device__ __align__(16) float g_tab[TAB_ROWS * NCOLS];              // layer-1 dedup table
__device__ __align__(16) int   g_map[N_NODES];                       // node -> table row
__device__ __align__(16) int   g_cnt[N_NODES * N_REL];
__device__ __align__(16) float g_Wbig[2][DIM * NCOLS];
__device__ __align__(16) float g_cread[DIM];
__device__ __align__(16) float g_h[DIM];

// ---------------- packed fp32 helpers (Blackwell FFMA2 via PTX f32x2) ----------------
__device__ __forceinline__ unsigned long long fma2(unsigned long long a,
                                                   unsigned long long b,
                                                   unsigned long long c)
{
    unsigned long long d;
    asm("fma.rn.f32x2 %0, %1, %2, %3;" : "=l"(d) : "l"(a), "l"(b), "l"(c));
    return d;
}
__device__ __forceinline__ float2 u2f(unsigned long long u)
{
    float2 f;
    asm("mov.b64 {%0, %1}, %2;" : "=f"(f.x), "=f"(f.y) : "l"(u));
    return f;
}

// ---------------- repack W: Wbig[d*1152 + c] = [W_r | root] ----------------
__global__ void prep_wbig_kernel(const float* __restrict__ W,
                                 const float* __restrict__ root,
                                 float* __restrict__ out)
{
    int idx = blockIdx.x * blockDim.x + threadIdx.x;
    if (idx >= DIM * NCOLS) return;
    int d = idx / NCOLS;
    int c = idx % NCOLS;
    float v;
    if (c < NRD) {
        int r = c >> 7, o = c & 127;
        v = W[(size_t)r * DIM * DIM + d * DIM + o];
    } else {
        v = root[d * DIM + (c - NRD)];
    }
    out[idx] = v;
}

// ---------------- node -> embedding-table row map ----------------
__global__ void map_kernel(const int* __restrict__ diag_idx,
                           const int* __restrict__ pro_idx)
{
    int n = blockIdx.x * blockDim.x + threadIdx.x;
    if (n >= N_NODES) return;
    int m;
    if (n < N_DIAG) m = min(max(diag_idx[n], 0), VOC_DIAG - 1);
    else            m = VOC_DIAG + min(max(pro_idx[n - N_DIAG], 0), VOC_PRO - 1);
    g_map[n] = m;
}

// ---------------- layer-1 y init: y[n] = tab[map[n], root block] (bias baked in) ----
__global__ void yinit_kernel()
{
    int i = blockIdx.x * blockDim.x + threadIdx.x;   // over N_NODES * 32 float4s
    if (i >= N_NODES * 32) return;
    int node = i >> 5;
    int f4   = i & 31;
    const float4* srow = (const float4*)(g_tab + (size_t)g_map[node] * NCOLS + NRD);
    ((float4*)(g_y + (size_t)node * DIM))[f4] = srow[f4];
}

// ---------------- histogram of (dst, etype) ----------------
__global__ void hist_kernel(const int* __restrict__ dst, const int* __restrict__ et)
{
    int e = blockIdx.x * blockDim.x + threadIdx.x;
    if (e >= N_EDGES) return;
    int d = min(max(dst[e], 0), N_NODES - 1);
    int r = et[e] & (N_REL - 1);
    atomicAdd(&g_cnt[d * N_REL + r], 1);
}

// ======== table GEMM (3500 rows; small, kept in plain-FMA form) ====
#define T_BM 128
#define T_BN 64
#define T_BK 32
#define TAB_GRID_X (NCOLS / T_BN)                      // 18
#define TAB_GRID_Y ((TAB_ROWS + T_BM - 1) / T_BM)      // 28
__global__ __launch_bounds__(256)
void tabgemm_kernel(const float* __restrict__ diag_emb,
                    const float* __restrict__ pro_emb,
                    const float* __restrict__ Bmat,
                    const float* __restrict__ bias)
{
    __shared__ float As[T_BK][T_BM + 4];
    __shared__ float Bs[T_BK][T_BN];

    const int block_m = blockIdx.y * T_BM;
    const int block_n = blockIdx.x * T_BN;
    const int tid = threadIdx.x;
    const int tx = tid & 15;
    const int ty = tid >> 4;

    float acc[8][4];
#pragma unroll
    for (int m = 0; m < 8; m++)
#pragma unroll
        for (int n = 0; n < 4; n++) acc[m][n] = 0.f;

    for (int kb = 0; kb < DIM; kb += T_BK) {
#pragma unroll
        for (int i = 0; i < 4; i++) {
            int fid = tid + i * 256;
            int r   = fid >> 3;
            int c   = (fid & 7) * 4;
            int row = block_m + r;
            float4 v = make_float4(0.f, 0.f, 0.f, 0.f);
            if (row < TAB_ROWS) {
                const float* srow = (row < VOC_DIAG)
                    ? diag_emb + (size_t)row * DIM
                    : pro_emb  + (size_t)(row - VOC_DIAG) * DIM;
                v = *(const float4*)(srow + kb + c);
            }
            As[c + 0][r] = v.x; As[c + 1][r] = v.y;
            As[c + 2][r] = v.z; As[c + 3][r] = v.w;
        }
#pragma unroll
        for (int i = 0; i < 2; i++) {
            int fid = tid + i * 256;
            int r   = fid >> 4;
            int c   = (fid & 15) * 4;
            *(float4*)(&Bs[r][c]) =
                *(const float4*)(Bmat + (size_t)(kb + r) * NCOLS + block_n + c);
        }
        __syncthreads();

#pragma unroll
        for (int k = 0; k < T_BK; k++) {
            float4 a0 = *(const float4*)(&As[k][ty * 8]);
            float4 a1 = *(const float4*)(&As[k][ty * 8 + 4]);
            float4 b  = *(const float4*)(&Bs[k][tx * 4]);
            float am[8] = {a0.x, a0.y, a0.z, a0.w, a1.x, a1.y, a1.z, a1.w};
#pragma unroll
            for (int m = 0; m < 8; m++) {
                acc[m][0] = fmaf(am[m], b.x, acc[m][0]);
                acc[m][1] = fmaf(am[m], b.y, acc[m][1]);
                acc[m][2] = fmaf(am[m], b.z, acc[m][2]);
                acc[m][3] = fmaf(am[m], b.w, acc[m][3]);
            }
        }
        __syncthreads();
    }

    const int col = block_n + tx * 4;
#pragma unroll
    for (int m = 0; m < 8; m++) {
        int row = block_m + ty * 8 + m;
        if (row >= TAB_ROWS) continue;
        float4 v = make_float4(acc[m][0], acc[m][1], acc[m][2], acc[m][3]);
        if (col >= NRD) {
            float4 bv = *(const float4*)(bias + (col - NRD));
            v.x += bv.x; v.y += bv.y; v.z += bv.z; v.w += bv.w;
        }
        *(float4*)(g_tab + (size_t)row * NCOLS + col) = v;
    }
}

// ======== layer-2 GEMM, FFMA2 edition ==================================
// [50000,128] x [128,1152]; 128x128 block tile, 16x16 threads, 8x8 per thread.
// A tile stored DUPLICATED in smem (As2[k][2m]={a,a}) so both FFMA2 operands
// come straight from ld.shared with zero per-k packing movs.
#define BM 128
#define BN 128
#define BK 16
#define GEMM_GRID_X (NCOLS / BN)                       // 9
#define GEMM_GRID_Y ((N_NODES + BM - 1) / BM)          // 391
__global__ __launch_bounds__(256)
void gemm_kernel(const float* __restrict__ A, const float* __restrict__ B,
                 const float* __restrict__ bias)
{
    __shared__ float As2[BK][2 * BM + 8];   // dup pairs, +8 pad
    __shared__ float Bs [BK][BN + 4];

    const int block_m = blockIdx.y * BM;
    const int block_n = blockIdx.x * BN;
    const int tid = threadIdx.x;
    const int tx = tid & 15;    // n: 8 cols each
    const int ty = tid >> 4;    // m: 8 rows each

    unsigned long long acc2[8][4];   // acc2[m][np] = {acc[m][2np], acc[m][2np+1]}
#pragma unroll
    for (int m = 0; m < 8; m++)
#pragma unroll
        for (int n = 0; n < 4; n++) acc2[m][n] = 0ull;

    for (int kb = 0; kb < DIM; kb += BK) {
        // A tile: 128 rows x 16 k -> 512 float4 over 256 threads, stored duplicated
#pragma unroll
        for (int i = 0; i < 2; i++) {
            int fid = tid + i * 256;          // 0..511
            int r   = fid >> 2;               // row 0..127
            int c   = (fid & 3) * 4;          // k offset 0,4,8,12
            float4 v = make_float4(0.f, 0.f, 0.f, 0.f);
            if (block_m + r < N_NODES)
                v = *(const float4*)(A + (size_t)(block_m + r) * DIM + kb + c);
            *(float2*)(&As2[c + 0][2 * r]) = make_float2(v.x, v.x);
            *(float2*)(&As2[c + 1][2 * r]) = make_float2(v.y, v.y);
            *(float2*)(&As2[c + 2][2 * r]) = make_float2(v.z, v.z);
            *(float2*)(&As2[c + 3][2 * r]) = make_float2(v.w, v.w);
        }
        // B tile: 16 k x 128 n -> 512 float4 over 256 threads
#pragma unroll
        for (int i = 0; i < 2; i++) {
            int fid = tid + i * 256;
            int r   = fid >> 5;               // k-row 0..15
            int c   = (fid & 31) * 4;         // 0..124
            *(float4*)(&Bs[r][c]) =
                *(const float4*)(B + (size_t)(kb + r) * NCOLS + block_n + c);
        }
        __syncthreads();

#pragma unroll
        for (int k = 0; k < BK; k++) {
            const ulonglong2* ap = (const ulonglong2*)(&As2[k][ty * 16]);
            ulonglong2 a01 = ap[0], a23 = ap[1], a45 = ap[2], a67 = ap[3];
            const ulonglong2* bp = (const ulonglong2*)(&Bs[k][tx * 8]);
            ulonglong2 bA = bp[0], bB = bp[1];
            unsigned long long am[8] = {a01.x, a01.y, a23.x, a23.y,
                                        a45.x, a45.y, a67.x, a67.y};
#pragma unroll
            for (int m = 0; m < 8; m++) {
                acc2[m][0] = fma2(am[m], bA.x, acc2[m][0]);
                acc2[m][1] = fma2(am[m], bA.y, acc2[m][1]);
                acc2[m][2] = fma2(am[m], bB.x, acc2[m][2]);
                acc2[m][3] = fma2(am[m], bB.y, acc2[m][3]);
            }
        }
        __syncthreads();
    }

    // epilogue: cols block_n+tx*8 .. +7; BN=128 so a block is entirely xw or root
    const int col0 = block_n + tx * 8;
#pragma unroll
    for (int m = 0; m < 8; m++) {
        int row = block_m + ty * 8 + m;
        if (row >= N_NODES) continue;
        float2 p0 = u2f(acc2[m][0]), p1 = u2f(acc2[m][1]);
        float2 p2 = u2f(acc2[m][2]), p3 = u2f(acc2[m][3]);
        float4 lo = make_float4(p0.x, p0.y, p1.x, p1.y);
        float4 hi = make_float4(p2.x, p2.y, p3.x, p3.y);
        if (col0 < NRD) {
            float4* dst = (float4*)(g_xw + (size_t)row * NRD + col0);
            dst[0] = lo; dst[1] = hi;
        } else {
            int cc = col0 - NRD;
            float4 b0 = *(const float4*)(bias + cc);
            float4 b1 = *(const float4*)(bias + cc + 4);
            lo.x += b0.x; lo.y += b0.y; lo.z += b0.z; lo.w += b0.w;
            hi.x += b1.x; hi.y += b1.y; hi.z += b1.z; hi.w += b1.w;
            float4* dst = (float4*)(g_y + (size_t)row * DIM + cc);
            dst[0] = lo; dst[1] = hi;
        }
    }
}

// ---------------- edge scatter: y[dst] += norm * XW[row(src), et] (warp/edge) ----
#define EDGE_BLOCKS ((int)(((long long)N_EDGES * 32 + 255) / 256))   // 100000
__global__ __launch_bounds__(256)
void edge_kernel(const int* __restrict__ src, const int* __restrict__ dst,
                 const int* __restrict__ et,
                 const float* __restrict__ XW, int row_stride, int use_map)
{
    int gtid = blockIdx.x * blockDim.x + threadIdx.x;
    int e    = gtid >> 5;
    int lane = gtid & 31;
    if (e >= N_EDGES) return;
    int s = min(max(__ldg(src + e), 0), N_NODES - 1);
    int d = min(max(__ldg(dst + e), 0), N_NODES - 1);
    int r = __ldg(et + e) & (N_REL - 1);
    if (use_map) s = __ldg(&g_map[s]);
    int cnt = __ldg(&g_cnt[d * N_REL + r]);
    float norm = 1.0f / (float)max(cnt, 1);
    float4 v = *(const float4*)(XW + (size_t)s * row_stride + r * DIM + lane * 4);
    v.x *= norm; v.y *= norm; v.z *= norm; v.w *= norm;
    float* p = g_y + (size_t)d * DIM + lane * 4;
    asm volatile("red.global.add.v4.f32 [%0], {%1, %2, %3, %4};"
                 :: "l"(p), "f"(v.x), "f"(v.y), "f"(v.z), "f"(v.w) : "memory");
}

// ---------------- relu (+ optional column-sum readout) ----------------
#define RELU_ROWS 32
#define RELU_BLOCKS ((N_NODES + RELU_ROWS - 1) / RELU_ROWS)         // 1563
__global__ void relu_kernel(int do_readout)
{
    int col  = threadIdx.x;              // 128
    int row0 = blockIdx.x * RELU_ROWS;
    float sum = 0.f;
#pragma unroll 4
    for (int i = 0; i < RELU_ROWS; i++) {
        int row = row0 + i;
        if (row >= N_NODES) break;
        float v = g_y[(size_t)row * DIM + col];
        v = fmaxf(v, 0.f);
        g_x[(size_t)row * DIM + col] = v;
        sum += v;
    }
    if (do_readout) atomicAdd(&g_cread[col], sum);
}

// ---------------- GRU cell (single block, 128 threads) ----------------
__global__ void gru_kernel(const float* __restrict__ Wih, const float* __restrict__ Whh,
                           const float* __restrict__ bih, const float* __restrict__ bhh)
{
    __shared__ float c[DIM], hh[DIM];
    int tid = threadIdx.x;
    c[tid]  = g_cread[tid];
    hh[tid] = g_h[tid];
    __syncthreads();

    float gi[3], gh[3];
#pragma unroll
    for (int g = 0; g < 3; g++) {
        int row = g * DIM + tid;
        float si = bih[row], sh = bhh[row];
        const float* wi = Wih + (size_t)row * DIM;
        const float* wh = Whh + (size_t)row * DIM;
        for (int d = 0; d < DIM; d++) {
            si = fmaf(c[d],  wi[d], si);
            sh = fmaf(hh[d], wh[d], sh);
        }
        gi[g] = si; gh[g] = sh;
    }
    float r = 1.0f / (1.0f + expf(-(gi[0] + gh[0])));
    float z = 1.0f / (1.0f + expf(-(gi[1] + gh[1])));
    float n = tanhf(gi[2] + r * gh[2]);
    float hn = (1.0f - z) * n + z * hh[tid];
    __syncthreads();
    g_h[tid] = hn;
}

// ---------------- output head (single block, 256 threads) ----------------
__global__ void out_kernel(const float* __restrict__ Wo1, const float* __restrict__ bo1,
                           const float* __restrict__ Wo2, const float* __restrict__ bo2,
                           float* __restrict__ out)
{
    __shared__ float hs[DIM], tmp[2 * DIM];
    int tid = threadIdx.x;
    if (tid < DIM) hs[tid] = g_h[tid];
    __syncthreads();
    {
        float a = bo1[tid];
        const float* w = Wo1 + (size_t)tid * DIM;
        for (int d = 0; d < DIM; d++) a = fmaf(hs[d], w[d], a);
        tmp[tid] = fmaxf(a, 0.f);
    }
    __syncthreads();
    if (tid < VOC3) {
        float o = bo2[tid];
        const float* w = Wo2 + (size_t)tid * 2 * DIM;
        for (int j = 0; j < 2 * DIM; j++) o = fmaf(tmp[j], w[j], o);
        out[tid] = o;
    }
}

// =============================== host launcher ===============================
extern "C" void kernel_launch(void* const* d_in, const int* in_sizes, int n_in,
                              void* d_out, int out_size)
{
    const int*   c_diag_idx   = (const int*)  d_in[0];
    const int*   c_pro_idx    = (const int*)  d_in[1];
    const int*   c_edge_index = (const int*)  d_in[2];
    const int*   c_edge_type  = (const int*)  d_in[3];
    const float* diag_emb     = (const float*)d_in[4];
    const float* pro_emb      = (const float*)d_in[5];
    const float* W1           = (const float*)d_in[6];
    const float* root1        = (const float*)d_in[7];
    const float* b1           = (const float*)d_in[8];
    const float* W2           = (const float*)d_in[9];
    const float* root2        = (const float*)d_in[10];
    const float* b2           = (const float*)d_in[11];
    const float* gru_Wih      = (const float*)d_in[12];
    const float* gru_Whh      = (const float*)d_in[13];
    const float* gru_bih      = (const float*)d_in[14];
    const float* gru_bhh      = (const float*)d_in[15];
    const float* Wo1          = (const float*)d_in[16];
    const float* bo1          = (const float*)d_in[17];
    const float* Wo2          = (const float*)d_in[18];
    const float* bo2          = (const float*)d_in[19];
    float* out = (float*)d_out;

    void *p_x, *p_tab, *p_xw, *p_cnt, *p_cread, *p_h, *p_wbig;
    cudaGetSymbolAddress(&p_x,     g_x);
    cudaGetSymbolAddress(&p_tab,   g_tab);
    cudaGetSymbolAddress(&p_xw,    g_xw);
    cudaGetSymbolAddress(&p_cnt,   g_cnt);
    cudaGetSymbolAddress(&p_cread, g_cread);
    cudaGetSymbolAddress(&p_h,     g_h);
    cudaGetSymbolAddress(&p_wbig,  g_Wbig);
    const float* x_dev   = (const float*)p_x;
    const float* tab_dev = (const float*)p_tab;
    const float* xw_dev  = (const float*)p_xw;
    float* wbig0 = (float*)p_wbig;
    float* wbig1 = wbig0 + DIM * NCOLS;

    // once per call: repack weights; build layer-1 dedup table (visit-independent)
    {
        int n = DIM * NCOLS;
        prep_wbig_kernel<<<(n + 255) / 256, 256>>>(W1, root1, wbig0);
        prep_wbig_kernel<<<(n + 255) / 256, 256>>>(W2, root2, wbig1);
    }
    tabgemm_kernel<<<dim3(TAB_GRID_X, TAB_GRID_Y), 256>>>(diag_emb, pro_emb, wbig0, b1);
    cudaMemsetAsync(p_h, 0, DIM * sizeof(float));

    for (int t = 0; t < T_VISITS; t++) {
        const int* diag_t = c_diag_idx + (size_t)t * N_DIAG;
        const int* pro_t  = c_pro_idx  + (size_t)t * N_PRO;
        const int* src_t  = c_edge_index + (size_t)t * 2 * N_EDGES;
        const int* dst_t  = src_t + N_EDGES;
        const int* et_t   = c_edge_type + (size_t)t * N_EDGES;

        map_kernel<<<(N_NODES + 255) / 256, 256>>>(diag_t, pro_t);

        cudaMemsetAsync(p_cnt, 0, N_NODES * N_REL * sizeof(int));
        hist_kernel<<<(N_EDGES + 255) / 256, 256>>>(dst_t, et_t);
        cudaMemsetAsync(p_cread, 0, DIM * sizeof(float));

        // ---- layer 1 (deduplicated via table) ----
        yinit_kernel<<<(N_NODES * 32 + 255) / 256, 256>>>();
        edge_kernel<<<EDGE_BLOCKS, 256>>>(src_t, dst_t, et_t, tab_dev, NCOLS, 1);
        relu_kernel<<<RELU_BLOCKS, DIM>>>(0);

        // ---- layer 2 (full GEMM, FFMA2) ----
        gemm_kernel<<<dim3(GEMM_GRID_X, GEMM_GRID_Y), 256>>>(x_dev, wbig1, b2);
        edge_kernel<<<EDGE_BLOCKS, 256>>>(src_t, dst_t, et_t, xw_dev, NRD, 0);
        relu_kernel<<<RELU_BLOCKS, DIM>>>(1);

        gru_kernel<<<1, DIM>>>(gru_Wih, gru_Whh, gru_bih, gru_bhh);
    }
    out_kernel<<<1, 2 * DIM>>>(Wo1, bo1, Wo2, bo2, out);
}

// round 10
// speedup vs baseline: 1.7907x; 1.0990x over previous
#include <cuda_runtime.h>
#include <cuda_bf16.h>
#include <math.h>
#include <stdint.h>

#define DIM      128
#define N_DIAG   30000
#define N_PRO    20000
#define N_NODES  50000
#define N_EDGES  800000
#define N_REL    8
#define T_VISITS 2
#define NCOLS    (N_REL * DIM + DIM)   // 1152: 8 relation blocks + root block
#define NRD      (N_REL * DIM)         // 1024
#define VOC_DIAG 2000
#define VOC_PRO  1500
#define TAB_ROWS (VOC_DIAG + VOC_PRO)  // 3500 distinct embedding rows
#define VOC3     150

// RULES LEARNED (hard way):
//  1. NO CUDA API calls before main() — pre-registration runtime init leaves this
//     module's kernels unloadable ("invalid resource handle" on every launch).
//  2. NO register caps that cause spills — ~448 B/thread spill grew the driver
//     local-memory pool by 134 MiB at first launch -> harness checkpoint violation.
//  3. From HOST code, pass device globals via cudaGetSymbolAddress, never by name.
__device__ __align__(16) float g_x  [N_NODES * DIM];                 // layer output (relu'd)
__device__ __align__(16) float g_y  [N_NODES * DIM];                 // layer-2 root part
__device__ __align__(16) float g_xw [(size_t)N_NODES * N_REL * DIM]; // layer-2 transforms
__device__ __align__(16) float g_tab[TAB_ROWS * NCOLS];              // layer-1 dedup table
__device__ __align__(16) int   g_map[N_NODES];                       // node -> table row
__device__ __align__(16) int   g_cnt[N_NODES * N_REL];               // (dst,rel) counts
__device__ __align__(16) int   g_off[N_NODES + 1];                   // CSR row offsets
__device__ __align__(16) int   g_pos[N_NODES];                       // scatter cursors
__device__ __align__(16) int   g_epk[N_EDGES];                       // packed src|et|map
__device__ __align__(16) float g_Wbig[2][DIM * NCOLS];
__device__ __align__(16) float g_cread[DIM];
__device__ __align__(16) float g_h[DIM];

// ---------------- packed fp32 helpers (Blackwell FFMA2 via PTX f32x2) ----------------
__device__ __forceinline__ unsigned long long fma2(unsigned long long a,
                                                   unsigned long long b,
                                                   unsigned long long c)
{
    unsigned long long d;
    asm("fma.rn.f32x2 %0, %1, %2, %3;" : "=l"(d) : "l"(a), "l"(b), "l"(c));
    return d;
}
__device__ __forceinline__ float2 u2f(unsigned long long u)
{
    float2 f;
    asm("mov.b64 {%0, %1}, %2;" : "=f"(f.x), "=f"(f.y) : "l"(u));
    return f;
}

// ---------------- repack W: Wbig[d*1152 + c] = [W_r | root] ----------------
__global__ void prep_wbig_kernel(const float* __restrict__ W,
                                 const float* __restrict__ root,
                                 float* __restrict__ out)
{
    int idx = blockIdx.x * blockDim.x + threadIdx.x;
    if (idx >= DIM * NCOLS) return;
    int d = idx / NCOLS;
    int c = idx % NCOLS;
    float v;
    if (c < NRD) {
        int r = c >> 7, o = c & 127;
        v = W[(size_t)r * DIM * DIM + d * DIM + o];
    } else {
        v = root[d * DIM + (c - NRD)];
    }
    out[idx] = v;
}

// ---------------- node -> embedding-table row map ----------------
__global__ void map_kernel(const int* __restrict__ diag_idx,
                           const int* __restrict__ pro_idx)
{
    int n = blockIdx.x * blockDim.x + threadIdx.x;
    if (n >= N_NODES) return;
    int m;
    if (n < N_DIAG) m = min(max(diag_idx[n], 0), VOC_DIAG - 1);
    else            m = VOC_DIAG + min(max(pro_idx[n - N_DIAG], 0), VOC_PRO - 1);
    g_map[n] = m;
}

// ---------------- histogram of (dst, etype) ----------------
__global__ void hist_kernel(const int* __restrict__ dst, const int* __restrict__ et)
{
    int e = blockIdx.x * blockDim.x + threadIdx.x;
    if (e >= N_EDGES) return;
    int d = min(max(dst[e], 0), N_NODES - 1);
    int r = et[e] & (N_REL - 1);
    atomicAdd(&g_cnt[d * N_REL + r], 1);
}

// ---------------- exclusive prefix scan of per-dst edge totals (1 block) ----------------
#define SCAN_T 1024
__global__ __launch_bounds__(SCAN_T)
void scan_kernel()
{
    __shared__ int sdata[SCAN_T];
    __shared__ int carry;
    int tid = threadIdx.x;
    if (tid == 0) carry = 0;
    __syncthreads();
    for (int base = 0; base < N_NODES; base += SCAN_T) {
        int d = base + tid;
        int v = 0;
        if (d < N_NODES) {
#pragma unroll
            for (int r = 0; r < N_REL; r++) v += g_cnt[d * N_REL + r];
        }
        sdata[tid] = v;
        __syncthreads();
        for (int ofs = 1; ofs < SCAN_T; ofs <<= 1) {
            int t = (tid >= ofs) ? sdata[tid - ofs] : 0;
            __syncthreads();
            sdata[tid] += t;
            __syncthreads();
        }
        int incl = sdata[tid];
        int excl = incl - v;
        if (d < N_NODES) {
            g_off[d] = carry + excl;
            g_pos[d] = carry + excl;
        }
        __syncthreads();
        if (tid == SCAN_T - 1) carry += incl;   // block total
        __syncthreads();
    }
    if (tid == 0) g_off[N_NODES] = carry;       // == N_EDGES
}

// ---------------- scatter edges into CSR; pack src|et|map[src] into one int ----------
__global__ void scatter_kernel(const int* __restrict__ src, const int* __restrict__ dst,
                               const int* __restrict__ et)
{
    int e = blockIdx.x * blockDim.x + threadIdx.x;
    if (e >= N_EDGES) return;
    int d = min(max(__ldg(dst + e), 0), N_NODES - 1);
    int s = min(max(__ldg(src + e), 0), N_NODES - 1);
    int r = __ldg(et + e) & (N_REL - 1);
    int m = __ldg(&g_map[s]);                   // 0..3499, 12 bits
    int p = atomicAdd(&g_pos[d], 1);
    g_epk[p] = s | (r << 16) | (m << 19);       // 16 + 3 + 12 = 31 bits
}

// ---------------- CSR gather: warp per dst, zero atomics ----------------
// out x[d] = relu( root_d + sum_{edges(d)} norm * XW[row(src), et] )
// layer1: row = map-bits of pk, stride NCOLS, root from tab[map[d], root block]
// layer2: row = src-bits of pk, stride NRD,   root from g_y[d]
#define GATHER_BLOCKS ((N_NODES + 7) / 8)       // 8 warps per 256-thread block
__global__ __launch_bounds__(256)
void gather_kernel(const float* __restrict__ XW, int row_stride, int layer1)
{
    int gw   = (blockIdx.x * 256 + threadIdx.x) >> 5;
    int lane = threadIdx.x & 31;
    if (gw >= N_NODES) return;
    const int d = gw;

    int b  = __ldg(&g_off[d]);
    int e2 = __ldg(&g_off[d + 1]);

    float nv = 0.f;
    if (lane < N_REL) {
        int c = __ldg(&g_cnt[d * N_REL + lane]);
        nv = 1.0f / (float)max(c, 1);
    }

    float4 acc = make_float4(0.f, 0.f, 0.f, 0.f);

#define GACC(pk) do {                                                        \
        int s_ = layer1 ? ((pk) >> 19) : ((pk) & 0xFFFF);                     \
        int r_ = ((pk) >> 16) & 7;                                            \
        float nm = __shfl_sync(0xFFFFFFFFu, nv, r_);                          \
        float4 v_ = *(const float4*)(XW + (size_t)s_ * row_stride             \
                                     + r_ * DIM + lane * 4);                  \
        acc.x += v_.x * nm; acc.y += v_.y * nm;                               \
        acc.z += v_.z * nm; acc.w += v_.w * nm;                               \
    } while (0)

    int i = b;
    for (; i + 4 <= e2; i += 4) {               // 4-deep MLP on the xw reads
        int pk0 = __ldg(g_epk + i + 0);
        int pk1 = __ldg(g_epk + i + 1);
        int pk2 = __ldg(g_epk + i + 2);
        int pk3 = __ldg(g_epk + i + 3);
        GACC(pk0); GACC(pk1); GACC(pk2); GACC(pk3);
    }
    for (; i < e2; i++) {
        int pk = __ldg(g_epk + i);
        GACC(pk);
    }
#undef GACC

    float4 base;
    if (layer1) {
        int m = __ldg(&g_map[d]);
        base = *(const float4*)(g_tab + (size_t)m * NCOLS + NRD + lane * 4);
    } else {
        base = *(const float4*)(g_y + (size_t)d * DIM + lane * 4);
    }
    float4 o;
    o.x = fmaxf(base.x + acc.x, 0.f);
    o.y = fmaxf(base.y + acc.y, 0.f);
    o.z = fmaxf(base.z + acc.z, 0.f);
    o.w = fmaxf(base.w + acc.w, 0.f);
    *(float4*)(g_x + (size_t)d * DIM + lane * 4) = o;
}

// ======== table GEMM (3500 rows; small, plain-FMA form) ====
#define T_BM 128
#define T_BN 64
#define T_BK 32
#define TAB_GRID_X (NCOLS / T_BN)                      // 18
#define TAB_GRID_Y ((TAB_ROWS + T_BM - 1) / T_BM)      // 28
__global__ __launch_bounds__(256)
void tabgemm_kernel(const float* __restrict__ diag_emb,
                    const float* __restrict__ pro_emb,
                    const float* __restrict__ Bmat,
                    const float* __restrict__ bias)
{
    __shared__ float As[T_BK][T_BM + 4];
    __shared__ float Bs[T_BK][T_BN];

    const int block_m = blockIdx.y * T_BM;
    const int block_n = blockIdx.x * T_BN;
    const int tid = threadIdx.x;
    const int tx = tid & 15;
    const int ty = tid >> 4;

    float acc[8][4];
#pragma unroll
    for (int m = 0; m < 8; m++)
#pragma unroll
        for (int n = 0; n < 4; n++) acc[m][n] = 0.f;

    for (int kb = 0; kb < DIM; kb += T_BK) {
#pragma unroll
        for (int i = 0; i < 4; i++) {
            int fid = tid + i * 256;
            int r   = fid >> 3;
            int c   = (fid & 7) * 4;
            int row = block_m + r;
            float4 v = make_float4(0.f, 0.f, 0.f, 0.f);
            if (row < TAB_ROWS) {
                const float* srow = (row < VOC_DIAG)
                    ? diag_emb + (size_t)row * DIM
                    : pro_emb  + (size_t)(row - VOC_DIAG) * DIM;
                v = *(const float4*)(srow + kb + c);
            }
            As[c + 0][r] = v.x; As[c + 1][r] = v.y;
            As[c + 2][r] = v.z; As[c + 3][r] = v.w;
        }
#pragma unroll
        for (int i = 0; i < 2; i++) {
            int fid = tid + i * 256;
            int r   = fid >> 4;
            int c   = (fid & 15) * 4;
            *(float4*)(&Bs[r][c]) =
                *(const float4*)(Bmat + (size_t)(kb + r) * NCOLS + block_n + c);
        }
        __syncthreads();

#pragma unroll
        for (int k = 0; k < T_BK; k++) {
            float4 a0 = *(const float4*)(&As[k][ty * 8]);
            float4 a1 = *(const float4*)(&As[k][ty * 8 + 4]);
            float4 b  = *(const float4*)(&Bs[k][tx * 4]);
            float am[8] = {a0.x, a0.y, a0.z, a0.w, a1.x, a1.y, a1.z, a1.w};
#pragma unroll
            for (int m = 0; m < 8; m++) {
                acc[m][0] = fmaf(am[m], b.x, acc[m][0]);
                acc[m][1] = fmaf(am[m], b.y, acc[m][1]);
                acc[m][2] = fmaf(am[m], b.z, acc[m][2]);
                acc[m][3] = fmaf(am[m], b.w, acc[m][3]);
            }
        }
        __syncthreads();
    }

    const int col = block_n + tx * 4;
#pragma unroll
    for (int m = 0; m < 8; m++) {
        int row = block_m + ty * 8 + m;
        if (row >= TAB_ROWS) continue;
        float4 v = make_float4(acc[m][0], acc[m][1], acc[m][2], acc[m][3]);
        if (col >= NRD) {
            float4 bv = *(const float4*)(bias + (col - NRD));
            v.x += bv.x; v.y += bv.y; v.z += bv.z; v.w += bv.w;
        }
        *(float4*)(g_tab + (size_t)row * NCOLS + col) = v;
    }
}

// ======== layer-2 GEMM, FFMA2 edition (unchanged from R9 — known good) ============
#define BM 128
#define BN 128
#define BK 16
#define GEMM_GRID_X (NCOLS / BN)                       // 9
#define GEMM_GRID_Y ((N_NODES + BM - 1) / BM)          // 391
__global__ __launch_bounds__(256)
void gemm_kernel(const float* __restrict__ A, const float* __restrict__ B,
                 const float* __restrict__ bias)
{
    __shared__ float As2[BK][2 * BM + 8];
    __shared__ float Bs [BK][BN + 4];

    const int block_m = blockIdx.y * BM;
    const int block_n = blockIdx.x * BN;
    const int tid = threadIdx.x;
    const int tx = tid & 15;
    const int ty = tid >> 4;

    unsigned long long acc2[8][4];
#pragma unroll
    for (int m = 0; m < 8; m++)
#pragma unroll
        for (int n = 0; n < 4; n++) acc2[m][n] = 0ull;

    for (int kb = 0; kb < DIM; kb += BK) {
#pragma unroll
        for (int i = 0; i < 2; i++) {
            int fid = tid + i * 256;
            int r   = fid >> 2;
            int c   = (fid & 3) * 4;
            float4 v = make_float4(0.f, 0.f, 0.f, 0.f);
            if (block_m + r < N_NODES)
                v = *(const float4*)(A + (size_t)(block_m + r) * DIM + kb + c);
            *(float2*)(&As2[c + 0][2 * r]) = make_float2(v.x, v.x);
            *(float2*)(&As2[c + 1][2 * r]) = make_float2(v.y, v.y);
            *(float2*)(&As2[c + 2][2 * r]) = make_float2(v.z, v.z);
            *(float2*)(&As2[c + 3][2 * r]) = make_float2(v.w, v.w);
        }
#pragma unroll
        for (int i = 0; i < 2; i++) {
            int fid = tid + i * 256;
            int r   = fid >> 5;
            int c   = (fid & 31) * 4;
            *(float4*)(&Bs[r][c]) =
                *(const float4*)(B + (size_t)(kb + r) * NCOLS + block_n + c);
        }
        __syncthreads();

#pragma unroll
        for (int k = 0; k < BK; k++) {
            const ulonglong2* ap = (const ulonglong2*)(&As2[k][ty * 16]);
            ulonglong2 a01 = ap[0], a23 = ap[1], a45 = ap[2], a67 = ap[3];
            const ulonglong2* bp = (const ulonglong2*)(&Bs[k][tx * 8]);
            ulonglong2 bA = bp[0], bB = bp[1];
            unsigned long long am[8] = {a01.x, a01.y, a23.x, a23.y,
                                        a45.x, a45.y, a67.x, a67.y};
#pragma unroll
            for (int m = 0; m < 8; m++) {
                acc2[m][0] = fma2(am[m], bA.x, acc2[m][0]);
                acc2[m][1] = fma2(am[m], bA.y, acc2[m][1]);
                acc2[m][2] = fma2(am[m], bB.x, acc2[m][2]);
                acc2[m][3] = fma2(am[m], bB.y, acc2[m][3]);
            }
        }
        __syncthreads();
    }

    const int col0 = block_n + tx * 8;
#pragma unroll
    for (int m = 0; m < 8; m++) {
        int row = block_m + ty * 8 + m;
        if (row >= N_NODES) continue;
        float2 p0 = u2f(acc2[m][0]), p1 = u2f(acc2[m][1]);
        float2 p2 = u2f(acc2[m][2]), p3 = u2f(acc2[m][3]);
        float4 lo = make_float4(p0.x, p0.y, p1.x, p1.y);
        float4 hi = make_float4(p2.x, p2.y, p3.x, p3.y);
        if (col0 < NRD) {
            float4* dst = (float4*)(g_xw + (size_t)row * NRD + col0);
            dst[0] = lo; dst[1] = hi;
        } else {
            int cc = col0 - NRD;
            float4 b0 = *(const float4*)(bias + cc);
            float4 b1 = *(const float4*)(bias + cc + 4);
            lo.x += b0.x; lo.y += b0.y; lo.z += b0.z; lo.w += b0.w;
            hi.x += b1.x; hi.y += b1.y; hi.z += b1.z; hi.w += b1.w;
            float4* dst = (float4*)(g_y + (size_t)row * DIM + cc);
            dst[0] = lo; dst[1] = hi;
        }
    }
}

// ---------------- readout: cread += column sums of g_x ----------------
#define RO_ROWS 32
#define RO_BLOCKS ((N_NODES + RO_ROWS - 1) / RO_ROWS)
__global__ void readout_kernel()
{
    int col  = threadIdx.x;              // 128
    int row0 = blockIdx.x * RO_ROWS;
    float sum = 0.f;
#pragma unroll 4
    for (int i = 0; i < RO_ROWS; i++) {
        int row = row0 + i;
        if (row >= N_NODES) break;
        sum += g_x[(size_t)row * DIM + col];
    }
    atomicAdd(&g_cread[col], sum);
}

// ---------------- GRU cell (single block, 128 threads) ----------------
__global__ void gru_kernel(const float* __restrict__ Wih, const float* __restrict__ Whh,
                           const float* __restrict__ bih, const float* __restrict__ bhh)
{
    __shared__ float c[DIM], hh[DIM];
    int tid = threadIdx.x;
    c[tid]  = g_cread[tid];
    hh[tid] = g_h[tid];
    __syncthreads();

    float gi[3], gh[3];
#pragma unroll
    for (int g = 0; g < 3; g++) {
        int row = g * DIM + tid;
        float si = bih[row], sh = bhh[row];
        const float* wi = Wih + (size_t)row * DIM;
        const float* wh = Whh + (size_t)row * DIM;
        for (int d = 0; d < DIM; d++) {
            si = fmaf(c[d],  wi[d], si);
            sh = fmaf(hh[d], wh[d], sh);
        }
        gi[g] = si; gh[g] = sh;
    }
    float r = 1.0f / (1.0f + expf(-(gi[0] + gh[0])));
    float z = 1.0f / (1.0f + expf(-(gi[1] + gh[1])));
    float n = tanhf(gi[2] + r * gh[2]);
    float hn = (1.0f - z) * n + z * hh[tid];
    __syncthreads();
    g_h[tid] = hn;
}

// ---------------- output head (single block, 256 threads) ----------------
__global__ void out_kernel(const float* __restrict__ Wo1, const float* __restrict__ bo1,
                           const float* __restrict__ Wo2, const float* __restrict__ bo2,
                           float* __restrict__ out)
{
    __shared__ float hs[DIM], tmp[2 * DIM];
    int tid = threadIdx.x;
    if (tid < DIM) hs[tid] = g_h[tid];
    __syncthreads();
    {
        float a = bo1[tid];
        const float* w = Wo1 + (size_t)tid * DIM;
        for (int d = 0; d < DIM; d++) a = fmaf(hs[d], w[d], a);
        tmp[tid] = fmaxf(a, 0.f);
    }
    __syncthreads();
    if (tid < VOC3) {
        float o = bo2[tid];
        const float* w = Wo2 + (size_t)tid * 2 * DIM;
        for (int j = 0; j < 2 * DIM; j++) o = fmaf(tmp[j], w[j], o);
        out[tid] = o;
    }
}

// =============================== host launcher ===============================
extern "C" void kernel_launch(void* const* d_in, const int* in_sizes, int n_in,
                              void* d_out, int out_size)
{
    const int*   c_diag_idx   = (const int*)  d_in[0];
    const int*   c_pro_idx    = (const int*)  d_in[1];
    const int*   c_edge_index = (const int*)  d_in[2];
    const int*   c_edge_type  = (const int*)  d_in[3];
    const float* diag_emb     = (const float*)d_in[4];
    const float* pro_emb      = (const float*)d_in[5];
    const float* W1           = (const float*)d_in[6];
    const float* root1        = (const float*)d_in[7];
    const float* b1           = (const float*)d_in[8];
    const float* W2           = (const float*)d_in[9];
    const float* root2        = (const float*)d_in[10];
    const float* b2           = (const float*)d_in[11];
    const float* gru_Wih      = (const float*)d_in[12];
    const float* gru_Whh      = (const float*)d_in[13];
    const float* gru_bih      = (const float*)d_in[14];
    const float* gru_bhh      = (const float*)d_in[15];
    const float* Wo1          = (const float*)d_in[16];
    const float* bo1          = (const float*)d_in[17];
    const float* Wo2          = (const float*)d_in[18];
    const float* bo2          = (const float*)d_in[19];
    float* out = (float*)d_out;

    void *p_x, *p_tab, *p_xw, *p_cnt, *p_cread, *p_h, *p_wbig;
    cudaGetSymbolAddress(&p_x,     g_x);
    cudaGetSymbolAddress(&p_tab,   g_tab);
    cudaGetSymbolAddress(&p_xw,    g_xw);
    cudaGetSymbolAddress(&p_cnt,   g_cnt);
    cudaGetSymbolAddress(&p_cread, g_cread);
    cudaGetSymbolAddress(&p_h,     g_h);
    cudaGetSymbolAddress(&p_wbig,  g_Wbig);
    const float* x_dev   = (const float*)p_x;
    const float* tab_dev = (const float*)p_tab;
    const float* xw_dev  = (const float*)p_xw;
    float* wbig0 = (float*)p_wbig;
    float* wbig1 = wbig0 + DIM * NCOLS;

    // once per call: repack weights; build layer-1 dedup table (visit-independent)
    {
        int n = DIM * NCOLS;
        prep_wbig_kernel<<<(n + 255) / 256, 256>>>(W1, root1, wbig0);
        prep_wbig_kernel<<<(n + 255) / 256, 256>>>(W2, root2, wbig1);
    }
    tabgemm_kernel<<<dim3(TAB_GRID_X, TAB_GRID_Y), 256>>>(diag_emb, pro_emb, wbig0, b1);
    cudaMemsetAsync(p_h, 0, DIM * sizeof(float));

    for (int t = 0; t < T_VISITS; t++) {
        const int* diag_t = c_diag_idx + (size_t)t * N_DIAG;
        const int* pro_t  = c_pro_idx  + (size_t)t * N_PRO;
        const int* src_t  = c_edge_index + (size_t)t * 2 * N_EDGES;
        const int* dst_t  = src_t + N_EDGES;
        const int* et_t   = c_edge_type + (size_t)t * N_EDGES;

        map_kernel<<<(N_NODES + 255) / 256, 256>>>(diag_t, pro_t);

        // ---- CSR build (shared by both layers) ----
        cudaMemsetAsync(p_cnt, 0, N_NODES * N_REL * sizeof(int));
        hist_kernel<<<(N_EDGES + 255) / 256, 256>>>(dst_t, et_t);
        scan_kernel<<<1, SCAN_T>>>();
        scatter_kernel<<<(N_EDGES + 255) / 256, 256>>>(src_t, dst_t, et_t);
        cudaMemsetAsync(p_cread, 0, DIM * sizeof(float));

        // ---- layer 1: dedup table + CSR gather (root+relu fused) ----
        gather_kernel<<<GATHER_BLOCKS, 256>>>(tab_dev, NCOLS, 1);

        // ---- layer 2: FFMA2 GEMM + CSR gather (root+relu fused) ----
        gemm_kernel<<<dim3(GEMM_GRID_X, GEMM_GRID_Y), 256>>>(x_dev, wbig1, b2);
        gather_kernel<<<GATHER_BLOCKS, 256>>>(xw_dev, NRD, 0);

        readout_kernel<<<RO_BLOCKS, DIM>>>();
        gru_kernel<<<1, DIM>>>(gru_Wih, gru_Whh, gru_bih, gru_bhh);
    }
    out_kernel<<<1, 2 * DIM>>>(Wo1, bo1, Wo2, bo2, out);
}